// round 2
// baseline (speedup 1.0000x reference)
#include <cuda_runtime.h>
#include <cstdint>

// Problem constants (fixed by the dataset)
#define NB    16
#define CH    256
#define LPIX  9216          // 96*96
#define NHEAD 8
#define HK    32            // CH / NHEAD
#define LT    64            // pixel tile per block
#define NLT   144           // LPIX / LT
#define XS_STRIDE 68        // 64 + 4 pad (keeps 16B row alignment, kills column conflicts)
#define WS_STRIDE 257       // 256 + 1 pad (conflict-free transposed W-tile stores)

// Scratch (allocation-free rule: __device__ globals)
__device__ float g_K[NB * CH * LPIX];            // 151 MB
__device__ float g_V[NB * CH * LPIX];            // 151 MB
__device__ float g_ctx[NB * NHEAD * HK * HK];    // normalized per-head context

// ---------------------------------------------------------------------------
// Fast exp on the FMA pipe (avoids MUFU throughput wall: 37.7M exps needed).
// exp(x) = 2^n * exp(t),  n = round(x*log2e), t = (x*log2e - n)*ln2, |t|<=0.347
// Taylor deg-5 remainder ~2.4e-6 rel. Valid for |x| < ~80 (we have |x| < ~10).
// ---------------------------------------------------------------------------
__device__ __forceinline__ float fexp(float x) {
    const float LOG2E = 1.4426950408889634f;
    const float SHIFT = 12582912.0f;             // 1.5 * 2^23
    float y = x * LOG2E;
    float z = __fadd_rn(y, SHIFT);
    int   n = __float_as_int(z) - 0x4B400000;
    float f = y - __fsub_rn(z, SHIFT);           // [-0.5, 0.5]
    float t = f * 0.6931471805599453f;
    float p = 1.0f + t * (1.0f + t * (0.5f + t * (0.16666667f +
              t * (0.041666667f + t * 0.0083333333f))));
    return __int_as_float((n + 127) << 23) * p;
}

// ---------------------------------------------------------------------------
// Shared GEMM tile: acc[8][8] += W(256xCH row-major, k-tile staged via Ws) @ Bs
// Block = 256 threads, output tile 256(cout) x 64(pix), BK = 32.
// Ws is stored transposed [k][o] with stride 257 -> conflict-free stores,
// broadcast-friendly compute reads. Bs rows are stride-68, 16B aligned.
// ---------------------------------------------------------------------------
__device__ __forceinline__ void gemm_tile_256x64(
    const float* __restrict__ W, float* Ws, const float* Bs,
    int ob, int pb, int tid, float acc[8][8])
{
    for (int kt = 0; kt < CH; kt += 32) {
        __syncthreads();                         // protect Ws from prior readers
        for (int i = tid; i < CH * 32; i += 256) {
            int k = i & 31;                      // lanes -> consecutive k: coalesced LDG
            int o = i >> 5;
            Ws[k * WS_STRIDE + o] = W[o * CH + kt + k];   // (k+o)%32 distinct: no conflicts
        }
        __syncthreads();
        #pragma unroll 4
        for (int kk = 0; kk < 32; ++kk) {
            float a[8];
            #pragma unroll
            for (int i = 0; i < 8; ++i) a[i] = Ws[kk * WS_STRIDE + ob + i];
            const float* brow = &Bs[(kt + kk) * XS_STRIDE + pb];
            float4 b0 = *reinterpret_cast<const float4*>(brow);
            float4 b1 = *reinterpret_cast<const float4*>(brow + 4);
            float b[8] = {b0.x, b0.y, b0.z, b0.w, b1.x, b1.y, b1.z, b1.w};
            #pragma unroll
            for (int i = 0; i < 8; ++i)
                #pragma unroll
                for (int j = 0; j < 8; ++j)
                    acc[i][j] += a[i] * b[j];
        }
    }
    __syncthreads();                             // next user may overwrite Ws/Bs
}

// ---------------------------------------------------------------------------
// Kernel 1: K = Wk@context + bk, V = Wv@context + bv.
// One block = one 64-pixel tile of one batch; context tile loaded ONCE into
// smem and reused for both projections. 2 blocks/SM.
// ---------------------------------------------------------------------------
__global__ void __launch_bounds__(256, 2)
proj_kv_kernel(const float* __restrict__ ctxt,
               const float* __restrict__ Wk, const float* __restrict__ bk,
               const float* __restrict__ Wv, const float* __restrict__ bv)
{
    const int lt = blockIdx.x, n = blockIdx.y;
    const int l0 = lt * LT;
    extern __shared__ float smem[];
    float* Xs = smem;                            // [256][68]
    float* Ws = smem + CH * XS_STRIDE;           // [32][257]
    const int tid = threadIdx.x;

    const float* src = ctxt + (size_t)n * CH * LPIX + l0;
    for (int i = tid; i < CH * LT / 4; i += 256) {
        int c  = i >> 4;
        int j4 = (i & 15) << 2;
        *reinterpret_cast<float4*>(&Xs[c * XS_STRIDE + j4]) =
            *reinterpret_cast<const float4*>(src + (size_t)c * LPIX + j4);
    }
    __syncthreads();

    const int tx = tid & 7, ty = tid >> 3;
    const int ob = ty * 8, pb = tx * 8;

    #pragma unroll 1
    for (int mat = 0; mat < 2; ++mat) {
        const float* W    = mat ? Wv : Wk;
        const float* bias = mat ? bv : bk;
        float* outp = (mat ? g_V : g_K) + (size_t)n * CH * LPIX + l0;

        float acc[8][8];
        #pragma unroll
        for (int i = 0; i < 8; ++i)
            #pragma unroll
            for (int j = 0; j < 8; ++j) acc[i][j] = 0.0f;

        gemm_tile_256x64(W, Ws, Xs, ob, pb, tid, acc);

        #pragma unroll
        for (int i = 0; i < 8; ++i) {
            float bo = __ldg(&bias[ob + i]);
            float* orow = outp + (size_t)(ob + i) * LPIX + pb;
            float4 r0 = make_float4(acc[i][0] + bo, acc[i][1] + bo,
                                    acc[i][2] + bo, acc[i][3] + bo);
            float4 r1 = make_float4(acc[i][4] + bo, acc[i][5] + bo,
                                    acc[i][6] + bo, acc[i][7] + bo);
            *reinterpret_cast<float4*>(orow)     = r0;
            *reinterpret_cast<float4*>(orow + 4) = r1;
        }
    }
}

// ---------------------------------------------------------------------------
// Kernel 2: per (n, head) block computes ctx[32][32] = softmax_L(K) @ V^T in
// ONE pass (normalize by row-sum of exp at the end). 256 threads, each owns a
// 2x2 (k,v) micro-tile; K/V streamed through smem in 128-wide chunks.
// ---------------------------------------------------------------------------
__global__ void ctx_kernel()
{
    const int h = blockIdx.x, n = blockIdx.y;
    __shared__ float eKs[HK * 132];              // stride 132: aligned + conflict-free
    __shared__ float Vs [HK * 132];
    __shared__ float ssum[HK];

    const int tid = threadIdx.x;
    const int kg = tid >> 4, vg = tid & 15;
    const int k0 = kg * 2,  v0 = vg * 2;

    float a00 = 0.f, a01 = 0.f, a10 = 0.f, a11 = 0.f;
    float s0 = 0.f, s1 = 0.f;

    const float* Kp = g_K + ((size_t)n * CH + h * HK) * LPIX;
    const float* Vp = g_V + ((size_t)n * CH + h * HK) * LPIX;

    for (int l0 = 0; l0 < LPIX; l0 += 128) {
        __syncthreads();
        for (int i = tid; i < HK * 128; i += 256) {
            int r = i >> 7, j = i & 127;
            eKs[r * 132 + j] = fexp(Kp[(size_t)r * LPIX + l0 + j]);
            Vs [r * 132 + j] =       Vp[(size_t)r * LPIX + l0 + j];
        }
        __syncthreads();
        #pragma unroll 4
        for (int j = 0; j < 128; j += 4) {
            float4 e0 = *reinterpret_cast<const float4*>(&eKs[ k0      * 132 + j]);
            float4 e1 = *reinterpret_cast<const float4*>(&eKs[(k0 + 1) * 132 + j]);
            float4 w0 = *reinterpret_cast<const float4*>(&Vs [ v0      * 132 + j]);
            float4 w1 = *reinterpret_cast<const float4*>(&Vs [(v0 + 1) * 132 + j]);
            a00 += e0.x*w0.x + e0.y*w0.y + e0.z*w0.z + e0.w*w0.w;
            a01 += e0.x*w1.x + e0.y*w1.y + e0.z*w1.z + e0.w*w1.w;
            a10 += e1.x*w0.x + e1.y*w0.y + e1.z*w0.z + e1.w*w0.w;
            a11 += e1.x*w1.x + e1.y*w1.y + e1.z*w1.z + e1.w*w1.w;
            if (vg == 0) {                       // one thread per k-pair owns row sums
                s0 += e0.x + e0.y + e0.z + e0.w;
                s1 += e1.x + e1.y + e1.z + e1.w;
            }
        }
    }
    if (vg == 0) { ssum[k0] = s0; ssum[k0 + 1] = s1; }
    __syncthreads();

    float i0 = 1.0f / ssum[k0];
    float i1 = 1.0f / ssum[k0 + 1];
    float* cg = g_ctx + (size_t)(n * NHEAD + h) * HK * HK;
    cg[ k0      * HK + v0    ] = a00 * i0;
    cg[ k0      * HK + v0 + 1] = a01 * i0;
    cg[(k0 + 1) * HK + v0    ] = a10 * i1;
    cg[(k0 + 1) * HK + v0 + 1] = a11 * i1;
}

// ---------------------------------------------------------------------------
// Kernel 3 (fully fused tail): per 64-pixel tile:
//   Q = Wq@x + bq  ->  per-(head,pixel) softmax over 32 channels
//   agg = ctx^T @ softmax(Q)  (in-place in Qs)
//   out = Wr@agg + br + x     (residual comes straight from the Xs tile)
// Input read once, output written once. 1 block/SM (205 KB smem).
// ---------------------------------------------------------------------------
__global__ void __launch_bounds__(256, 1)
att_out_kernel(const float* __restrict__ input,
               const float* __restrict__ Wq, const float* __restrict__ bq,
               const float* __restrict__ Wr, const float* __restrict__ br,
               float* __restrict__ out)
{
    const int lt = blockIdx.x, n = blockIdx.y;
    const int l0 = lt * LT;
    extern __shared__ float smem[];
    float* Xs = smem;                              // [256][68] input tile (kept for residual)
    float* Qs = Xs + CH * XS_STRIDE;               // [256][68] Q, then agg (in place)
    float* Ws = Qs + CH * XS_STRIDE;               // [32][257]
    float* Cs = Ws + 32 * WS_STRIDE;               // [8][32][32] normalized ctx
    const int tid = threadIdx.x;

    const float* ctxg = g_ctx + (size_t)n * NHEAD * HK * HK;
    for (int i = tid; i < NHEAD * HK * HK / 4; i += 256)
        reinterpret_cast<float4*>(Cs)[i] = reinterpret_cast<const float4*>(ctxg)[i];

    const float* xin = input + (size_t)n * CH * LPIX + l0;
    for (int i = tid; i < CH * LT / 4; i += 256) {
        int c  = i >> 4;
        int j4 = (i & 15) << 2;
        *reinterpret_cast<float4*>(&Xs[c * XS_STRIDE + j4]) =
            *reinterpret_cast<const float4*>(xin + (size_t)c * LPIX + j4);
    }
    __syncthreads();

    const int tx = tid & 7, ty = tid >> 3;
    const int ob = ty * 8, pb = tx * 8;

    // ---- GEMM 1: Qs = Wq @ Xs + bq ----
    {
        float acc[8][8];
        #pragma unroll
        for (int i = 0; i < 8; ++i)
            #pragma unroll
            for (int j = 0; j < 8; ++j) acc[i][j] = 0.0f;
        gemm_tile_256x64(Wq, Ws, Xs, ob, pb, tid, acc);
        #pragma unroll
        for (int i = 0; i < 8; ++i) {
            float bo = __ldg(&bq[ob + i]);
            float* qrow = &Qs[(ob + i) * XS_STRIDE + pb];
            #pragma unroll
            for (int j = 0; j < 8; ++j) qrow[j] = acc[i][j] + bo;
        }
    }
    __syncthreads();

    // ---- channel-softmax + ctx apply (in place, each thread owns 2 columns) ----
    #pragma unroll
    for (int r = 0; r < 2; ++r) {
        int item = tid + r * 256;                // 512 = 8 heads * 64 pixels
        int h = item >> 6, pix = item & 63;
        float q[HK];
        float s = 0.0f;
        #pragma unroll
        for (int k = 0; k < HK; ++k) {
            q[k] = fexp(Qs[(h * HK + k) * XS_STRIDE + pix]);
            s += q[k];
        }
        float inv = 1.0f / s;
        const float* ch = Cs + h * HK * HK;      // [k][v]
        #pragma unroll
        for (int vgp = 0; vgp < HK / 4; ++vgp) {
            float4 a = make_float4(0.f, 0.f, 0.f, 0.f);
            #pragma unroll 8
            for (int k = 0; k < HK; ++k) {
                float4 cv = *reinterpret_cast<const float4*>(&ch[k * HK + vgp * 4]);
                a.x += cv.x * q[k]; a.y += cv.y * q[k];
                a.z += cv.z * q[k]; a.w += cv.w * q[k];
            }
            Qs[(h * HK + vgp * 4 + 0) * XS_STRIDE + pix] = a.x * inv;
            Qs[(h * HK + vgp * 4 + 1) * XS_STRIDE + pix] = a.y * inv;
            Qs[(h * HK + vgp * 4 + 2) * XS_STRIDE + pix] = a.z * inv;
            Qs[(h * HK + vgp * 4 + 3) * XS_STRIDE + pix] = a.w * inv;
        }
    }
    __syncthreads();

    // ---- GEMM 2: out = Wr @ Qs(agg) + br + Xs(residual) ----
    {
        float acc[8][8];
        #pragma unroll
        for (int i = 0; i < 8; ++i)
            #pragma unroll
            for (int j = 0; j < 8; ++j) acc[i][j] = 0.0f;
        gemm_tile_256x64(Wr, Ws, Qs, ob, pb, tid, acc);
        #pragma unroll
        for (int i = 0; i < 8; ++i) {
            float bo = __ldg(&br[ob + i]);
            const float* xr = &Xs[(ob + i) * XS_STRIDE + pb];
            float* orow = out + (size_t)(n * CH + ob + i) * LPIX + l0 + pb;
            float4 r0 = make_float4(acc[i][0] + bo + xr[0], acc[i][1] + bo + xr[1],
                                    acc[i][2] + bo + xr[2], acc[i][3] + bo + xr[3]);
            float4 r1 = make_float4(acc[i][4] + bo + xr[4], acc[i][5] + bo + xr[5],
                                    acc[i][6] + bo + xr[6], acc[i][7] + bo + xr[7]);
            *reinterpret_cast<float4*>(orow)     = r0;
            *reinterpret_cast<float4*>(orow + 4) = r1;
        }
    }
}

// ---------------------------------------------------------------------------
extern "C" void kernel_launch(void* const* d_in, const int* in_sizes, int n_in,
                              void* d_out, int out_size)
{
    (void)in_sizes; (void)n_in; (void)out_size;
    const float* input_   = (const float*)d_in[0];
    const float* context_ = (const float*)d_in[1];
    const float* Wk = (const float*)d_in[2];
    const float* bk = (const float*)d_in[3];
    const float* Wq = (const float*)d_in[4];
    const float* bq = (const float*)d_in[5];
    const float* Wv = (const float*)d_in[6];
    const float* bv = (const float*)d_in[7];
    const float* Wr = (const float*)d_in[8];
    const float* br = (const float*)d_in[9];
    float* out = (float*)d_out;

    const int SMEM1 = (CH * XS_STRIDE + 32 * WS_STRIDE) * (int)sizeof(float);            // 102,528
    const int SMEM3 = (2 * CH * XS_STRIDE + 32 * WS_STRIDE + NHEAD * HK * HK)
                      * (int)sizeof(float);                                              // 204,928
    cudaFuncSetAttribute(proj_kv_kernel, cudaFuncAttributeMaxDynamicSharedMemorySize, SMEM1);
    cudaFuncSetAttribute(att_out_kernel, cudaFuncAttributeMaxDynamicSharedMemorySize, SMEM3);

    proj_kv_kernel<<<dim3(NLT, NB), 256, SMEM1>>>(context_, Wk, bk, Wv, bv);
    ctx_kernel   <<<dim3(NHEAD, NB), 256>>>();
    att_out_kernel<<<dim3(NLT, NB), 256, SMEM3>>>(input_, Wq, bq, Wr, br, out);
}

// round 4
// speedup vs baseline: 1.7066x; 1.7066x over previous
#include <cuda_runtime.h>
#include <cstdint>

// Problem constants (fixed by the dataset)
#define NB    16
#define CH    256
#define LPIX  9216          // 96*96
#define NHEAD 8
#define HK    32            // CH / NHEAD
#define LT    64            // pixel tile per block
#define NLT   144           // LPIX / LT
#define TS    72            // tile row stride (pixels + 8 pad): conflict-free mma B-frag loads
#define WST   36            // W k-tile stride (32 + 4 pad): conflict-free mma A-frag loads

// Global accumulators for the fused softmax-K context (allocation-free rule)
__device__ float g_num[NB * NHEAD * HK * HK];   // sum_l e^K[k,l] * V[v,l]
__device__ float g_den[NB * CH];                // sum_l e^K[k,l]

// ---------------------------------------------------------------------------
// Fast exp on the FMA pipe (37.7M exps; avoids MUFU throughput wall).
// ---------------------------------------------------------------------------
__device__ __forceinline__ float fexp(float x) {
    const float LOG2E = 1.4426950408889634f;
    const float SHIFT = 12582912.0f;             // 1.5 * 2^23
    float y = x * LOG2E;
    float z = __fadd_rn(y, SHIFT);
    int   n = __float_as_int(z) - 0x4B400000;
    float f = y - __fsub_rn(z, SHIFT);           // [-0.5, 0.5]
    float t = f * 0.6931471805599453f;
    float p = 1.0f + t * (1.0f + t * (0.5f + t * (0.16666667f +
              t * (0.041666667f + t * 0.0083333333f))));
    return __int_as_float((n + 127) << 23) * p;
}

// float -> tf32 (round to nearest) as raw b32 bits
__device__ __forceinline__ uint32_t f2tf32(float x) {
    uint32_t r;
    asm("cvt.rna.tf32.f32 %0, %1;" : "=r"(r) : "f"(x));
    return r;
}

// One m16n8k8 tf32 HMMA, C += A*B
__device__ __forceinline__ void mma8(float* c, const uint32_t* a, const uint32_t* b) {
    asm volatile(
        "mma.sync.aligned.m16n8k8.row.col.f32.tf32.tf32.f32 "
        "{%0,%1,%2,%3},{%4,%5,%6,%7},{%8,%9},{%0,%1,%2,%3};\n"
        : "+f"(c[0]), "+f"(c[1]), "+f"(c[2]), "+f"(c[3])
        : "r"(a[0]), "r"(a[1]), "r"(a[2]), "r"(a[3]), "r"(b[0]), "r"(b[1]));
}

// ---------------------------------------------------------------------------
// Tensor-core GEMM tile: C[256(cout) x 64(pix)] = W(256x256) @ Bs(256x64).
// 8 warps in a 4(cout) x 2(pix) grid; warp tile 64x32 = 4x4 m16n8 frags.
// W is staged per 32-wide k-slice into Ws (tf32, stride 36: conflict-free
// A-fragment loads). Bs rows are stride-72 (conflict-free B-fragment loads).
// CVT_B: convert Bs values f32->tf32 at fragment-load time (else pre-rounded).
// ---------------------------------------------------------------------------
template<bool CVT_B>
__device__ __forceinline__ void mma_gemm_256x64(
    const float* __restrict__ W, uint32_t* Ws, const uint32_t* Bs,
    int tid, float C[4][4][4])
{
    const int lane = tid & 31, q = lane >> 2, r = lane & 3;
    const int wid = tid >> 5;
    const int m_warp = (wid >> 1) * 64;
    const int n_warp = (wid & 1) * 32;

    for (int kt = 0; kt < CH; kt += 32) {
        __syncthreads();                          // everyone done with prior Ws
        #pragma unroll 4
        for (int i = tid; i < CH * 32; i += 256) {
            int k = i & 31, o = i >> 5;           // lanes -> consecutive k: coalesced
            Ws[o * WST + k] = f2tf32(W[o * CH + kt + k]);
        }
        __syncthreads();
        #pragma unroll
        for (int kk = 0; kk < 32; kk += 8) {
            uint32_t a[4][4], b[4][2];
            #pragma unroll
            for (int mi = 0; mi < 4; ++mi) {
                const uint32_t* ap = Ws + (m_warp + mi * 16 + q) * WST + kk + r;
                a[mi][0] = ap[0];
                a[mi][1] = ap[8 * WST];
                a[mi][2] = ap[4];
                a[mi][3] = ap[8 * WST + 4];
            }
            #pragma unroll
            for (int ni = 0; ni < 4; ++ni) {
                const uint32_t* bp = Bs + (kt + kk + r) * TS + n_warp + ni * 8 + q;
                uint32_t b0 = bp[0], b1 = bp[4 * TS];
                if (CVT_B) {
                    b0 = f2tf32(__uint_as_float(b0));
                    b1 = f2tf32(__uint_as_float(b1));
                }
                b[ni][0] = b0; b[ni][1] = b1;
            }
            #pragma unroll
            for (int mi = 0; mi < 4; ++mi)
                #pragma unroll
                for (int ni = 0; ni < 4; ++ni)
                    mma8(C[mi][ni], a[mi], b[ni]);
        }
    }
}

__device__ __forceinline__ void zeroC(float C[4][4][4]) {
    #pragma unroll
    for (int i = 0; i < 4; ++i)
        #pragma unroll
        for (int j = 0; j < 4; ++j)
            #pragma unroll
            for (int k = 0; k < 4; ++k) C[i][j][k] = 0.0f;
}

// ---------------------------------------------------------------------------
// Zero the cross-block context accumulators (runs first every launch/replay).
// ---------------------------------------------------------------------------
__global__ void zero_acc_kernel() {
    int i = blockIdx.x * blockDim.x + threadIdx.x;
    if (i < NB * NHEAD * HK * HK) g_num[i] = 0.0f;
    if (i < NB * CH)              g_den[i] = 0.0f;
}

// ---------------------------------------------------------------------------
// Kernel A (fused): per 64-pixel tile of one batch:
//   K = Wk@ctx + bk  (mma, tf32)  -> e^K into smem (Es)
//   V = Wv@ctx + bv  (mma)        -> Vs (reuses the context tile's smem)
//   per head: partial  num[32][32] = Es_h @ Vs_h^T  (mma over 64 pixels)
//             partial  den[k]      = row sums of Es
//   atomicAdd partials into g_num / g_den.
// K and V never touch HBM (saves 604 MB of traffic + a whole kernel).
// ---------------------------------------------------------------------------
__global__ void __launch_bounds__(256, 1)
fused_kv_ctx_kernel(const float* __restrict__ ctxt,
                    const float* __restrict__ Wk, const float* __restrict__ bk,
                    const float* __restrict__ Wv, const float* __restrict__ bv)
{
    const int lt = blockIdx.x, n = blockIdx.y;
    const int l0 = lt * LT;
    extern __shared__ uint32_t smemA[];
    uint32_t* Xs = smemA;                 // [256][72] tf32 context; later V (tf32)
    uint32_t* Es = Xs + CH * TS;          // [256][72] tf32 e^K
    uint32_t* Ws = Es + CH * TS;          // [256][36] staged W k-slice

    const int tid = threadIdx.x;
    const int wid = tid >> 5, lane = tid & 31, q = lane >> 2, r = lane & 3;
    const int m_warp = (wid >> 1) * 64, n_warp = (wid & 1) * 32;

    // Load context tile, rounding to tf32 once (only ever a GEMM operand)
    const float* src = ctxt + (size_t)n * CH * LPIX + l0;
    #pragma unroll 4
    for (int i = tid; i < CH * LT / 4; i += 256) {
        int c = i >> 4, j4 = (i & 15) << 2;
        float4 v = *reinterpret_cast<const float4*>(src + (size_t)c * LPIX + j4);
        uint4 u = make_uint4(f2tf32(v.x), f2tf32(v.y), f2tf32(v.z), f2tf32(v.w));
        *reinterpret_cast<uint4*>(&Xs[c * TS + j4]) = u;
    }

    float C[4][4][4];

    // ---- K projection -> e^K (tf32-rounded so num & den use identical values)
    zeroC(C);
    mma_gemm_256x64<false>(Wk, Ws, Xs, tid, C);
    #pragma unroll
    for (int mi = 0; mi < 4; ++mi) {
        int row = m_warp + mi * 16 + q;
        float b0v = __ldg(&bk[row]), b8v = __ldg(&bk[row + 8]);
        #pragma unroll
        for (int ni = 0; ni < 4; ++ni) {
            int col = n_warp + ni * 8 + 2 * r;
            Es[row * TS + col]           = f2tf32(fexp(C[mi][ni][0] + b0v));
            Es[row * TS + col + 1]       = f2tf32(fexp(C[mi][ni][1] + b0v));
            Es[(row + 8) * TS + col]     = f2tf32(fexp(C[mi][ni][2] + b8v));
            Es[(row + 8) * TS + col + 1] = f2tf32(fexp(C[mi][ni][3] + b8v));
        }
    }

    // ---- V projection (reads Xs) ...
    zeroC(C);
    mma_gemm_256x64<false>(Wv, Ws, Xs, tid, C);
    __syncthreads();                      // all warps done READING Xs
    // ... then overwrite Xs with V (tf32)
    #pragma unroll
    for (int mi = 0; mi < 4; ++mi) {
        int row = m_warp + mi * 16 + q;
        float b0v = __ldg(&bv[row]), b8v = __ldg(&bv[row + 8]);
        #pragma unroll
        for (int ni = 0; ni < 4; ++ni) {
            int col = n_warp + ni * 8 + 2 * r;
            Xs[row * TS + col]           = f2tf32(C[mi][ni][0] + b0v);
            Xs[row * TS + col + 1]       = f2tf32(C[mi][ni][1] + b0v);
            Xs[(row + 8) * TS + col]     = f2tf32(C[mi][ni][2] + b8v);
            Xs[(row + 8) * TS + col + 1] = f2tf32(C[mi][ni][3] + b8v);
        }
    }
    __syncthreads();                      // Es + Vs visible to all warps

    // ---- partial denominator: thread t sums e^K row t over 64 pixels
    {
        float s = 0.0f;
        const float* er = reinterpret_cast<const float*>(Es + tid * TS);
        #pragma unroll
        for (int p = 0; p < LT; p += 4) {
            float4 e = *reinterpret_cast<const float4*>(er + p);
            s += e.x + e.y + e.z + e.w;
        }
        atomicAdd(&g_den[n * CH + tid], s);
    }

    // ---- partial numerator: warp h computes num_h[32][32] = Es_h @ Vs_h^T
    {
        const int h = wid;
        float cc[2][4][4];
        #pragma unroll
        for (int i = 0; i < 2; ++i)
            #pragma unroll
            for (int j = 0; j < 4; ++j)
                #pragma unroll
                for (int k = 0; k < 4; ++k) cc[i][j][k] = 0.0f;

        const uint32_t* Eh = Es + (h * HK) * TS;   // A: [k-ch][pixel] row-major
        const uint32_t* Vh = Xs + (h * HK) * TS;   // B: [v-ch][pixel] (col form)
        #pragma unroll
        for (int kk = 0; kk < LT; kk += 8) {
            uint32_t a[2][4], b[4][2];
            #pragma unroll
            for (int mi = 0; mi < 2; ++mi) {
                const uint32_t* ap = Eh + (mi * 16 + q) * TS + kk + r;
                a[mi][0] = ap[0]; a[mi][1] = ap[8 * TS];
                a[mi][2] = ap[4]; a[mi][3] = ap[8 * TS + 4];
            }
            #pragma unroll
            for (int ni = 0; ni < 4; ++ni) {
                const uint32_t* bp = Vh + (ni * 8 + q) * TS + kk + r;
                b[ni][0] = bp[0]; b[ni][1] = bp[4];
            }
            #pragma unroll
            for (int mi = 0; mi < 2; ++mi)
                #pragma unroll
                for (int ni = 0; ni < 4; ++ni)
                    mma8(cc[mi][ni], a[mi], b[ni]);
        }

        float* base = g_num + ((size_t)(n * NHEAD + h) << 10);
        #pragma unroll
        for (int mi = 0; mi < 2; ++mi) {
            int k0 = mi * 16 + q;
            #pragma unroll
            for (int ni = 0; ni < 4; ++ni) {
                int v0 = ni * 8 + 2 * r;
                atomicAdd(base +  k0      * HK + v0,     cc[mi][ni][0]);
                atomicAdd(base +  k0      * HK + v0 + 1, cc[mi][ni][1]);
                atomicAdd(base + (k0 + 8) * HK + v0,     cc[mi][ni][2]);
                atomicAdd(base + (k0 + 8) * HK + v0 + 1, cc[mi][ni][3]);
            }
        }
    }
}

// ---------------------------------------------------------------------------
// Kernel B (fused tail): per 64-pixel tile:
//   Cs = g_num / g_den  (softmax-K normalization at consumption)
//   Q  = Wq@x + bq   (mma)  -> per-(head,pixel) softmax over 32 channels
//   agg = Cs^T @ softmax(Q)  (in place, tf32-rounded)
//   out = Wr@agg + br + x    (mma; residual straight from the smem tile)
// ---------------------------------------------------------------------------
__global__ void __launch_bounds__(256, 1)
tail_kernel(const float* __restrict__ input,
            const float* __restrict__ Wq, const float* __restrict__ bq,
            const float* __restrict__ Wr, const float* __restrict__ br,
            float* __restrict__ out)
{
    const int lt = blockIdx.x, n = blockIdx.y;
    const int l0 = lt * LT;
    extern __shared__ float smemB[];
    float*    Xs = smemB;                           // [256][72] fp32 input tile
    float*    Qs = Xs + CH * TS;                    // [256][72] Q, then agg
    uint32_t* Ws = reinterpret_cast<uint32_t*>(Qs + CH * TS);  // [256][36]
    float*    Cs = reinterpret_cast<float*>(Ws + CH * WST);    // [8][32][32]

    const int tid = threadIdx.x;
    const int wid = tid >> 5, lane = tid & 31, q = lane >> 2, r = lane & 3;
    const int m_warp = (wid >> 1) * 64, n_warp = (wid & 1) * 32;

    // Normalized per-head context
    {
        const float* numb = g_num + ((size_t)(n * NHEAD) << 10);
        const float* denb = g_den + n * CH;
        #pragma unroll 4
        for (int i = tid; i < NHEAD * HK * HK; i += 256) {
            int ch = i >> 5;                        // h*32 + k
            Cs[i] = __fdividef(numb[i], denb[ch]);
        }
    }

    // Input tile (fp32: residual needs full precision)
    const float* xin = input + (size_t)n * CH * LPIX + l0;
    #pragma unroll 4
    for (int i = tid; i < CH * LT / 4; i += 256) {
        int c = i >> 4, j4 = (i & 15) << 2;
        *reinterpret_cast<float4*>(&Xs[c * TS + j4]) =
            *reinterpret_cast<const float4*>(xin + (size_t)c * LPIX + j4);
    }

    float C[4][4][4];

    // ---- GEMM 1: Q = Wq @ Xs + bq (Xs is fp32 -> cvt at fragment load)
    zeroC(C);
    mma_gemm_256x64<true>(Wq, Ws, reinterpret_cast<const uint32_t*>(Xs), tid, C);
    #pragma unroll
    for (int mi = 0; mi < 4; ++mi) {
        int row = m_warp + mi * 16 + q;
        float b0v = __ldg(&bq[row]), b8v = __ldg(&bq[row + 8]);
        #pragma unroll
        for (int ni = 0; ni < 4; ++ni) {
            int col = n_warp + ni * 8 + 2 * r;
            Qs[row * TS + col]           = C[mi][ni][0] + b0v;
            Qs[row * TS + col + 1]       = C[mi][ni][1] + b0v;
            Qs[(row + 8) * TS + col]     = C[mi][ni][2] + b8v;
            Qs[(row + 8) * TS + col + 1] = C[mi][ni][3] + b8v;
        }
    }
    __syncthreads();

    // ---- channel softmax + context apply, in place (thread owns 2 columns)
    #pragma unroll
    for (int rep = 0; rep < 2; ++rep) {
        int item = tid + rep * 256;                 // 512 = 8 heads * 64 pixels
        int h = item >> 6, pix = item & 63;
        float qv[HK];
        float s = 0.0f;
        #pragma unroll
        for (int k = 0; k < HK; ++k) {
            qv[k] = fexp(Qs[(h * HK + k) * TS + pix]);
            s += qv[k];
        }
        float inv = 1.0f / s;
        const float* ch = Cs + h * HK * HK;         // [k][v]
        #pragma unroll
        for (int vg = 0; vg < HK / 4; ++vg) {
            float4 a = make_float4(0.f, 0.f, 0.f, 0.f);
            #pragma unroll 8
            for (int k = 0; k < HK; ++k) {
                float4 cv = *reinterpret_cast<const float4*>(&ch[k * HK + vg * 4]);
                a.x += cv.x * qv[k]; a.y += cv.y * qv[k];
                a.z += cv.z * qv[k]; a.w += cv.w * qv[k];
            }
            // store agg tf32-rounded: consumed only as GEMM2's B operand
            Qs[(h * HK + vg * 4 + 0) * TS + pix] = __uint_as_float(f2tf32(a.x * inv));
            Qs[(h * HK + vg * 4 + 1) * TS + pix] = __uint_as_float(f2tf32(a.y * inv));
            Qs[(h * HK + vg * 4 + 2) * TS + pix] = __uint_as_float(f2tf32(a.z * inv));
            Qs[(h * HK + vg * 4 + 3) * TS + pix] = __uint_as_float(f2tf32(a.w * inv));
        }
    }
    // (gemm's internal first __syncthreads orders these writes before B reads)

    // ---- GEMM 2: out = Wr @ agg + br + residual
    zeroC(C);
    mma_gemm_256x64<false>(Wr, Ws, reinterpret_cast<const uint32_t*>(Qs), tid, C);
    #pragma unroll
    for (int mi = 0; mi < 4; ++mi) {
        int row = m_warp + mi * 16 + q;
        float b0v = __ldg(&br[row]), b8v = __ldg(&br[row + 8]);
        #pragma unroll
        for (int ni = 0; ni < 4; ++ni) {
            int col = n_warp + ni * 8 + 2 * r;
            float* o0 = out + (size_t)(n * CH + row) * LPIX + l0 + col;
            float* o8 = out + (size_t)(n * CH + row + 8) * LPIX + l0 + col;
            float2 r0 = make_float2(C[mi][ni][0] + b0v + Xs[row * TS + col],
                                    C[mi][ni][1] + b0v + Xs[row * TS + col + 1]);
            float2 r8 = make_float2(C[mi][ni][2] + b8v + Xs[(row + 8) * TS + col],
                                    C[mi][ni][3] + b8v + Xs[(row + 8) * TS + col + 1]);
            *reinterpret_cast<float2*>(o0) = r0;
            *reinterpret_cast<float2*>(o8) = r8;
        }
    }
}

// ---------------------------------------------------------------------------
extern "C" void kernel_launch(void* const* d_in, const int* in_sizes, int n_in,
                              void* d_out, int out_size)
{
    (void)in_sizes; (void)n_in; (void)out_size;
    const float* input_   = (const float*)d_in[0];
    const float* context_ = (const float*)d_in[1];
    const float* Wk = (const float*)d_in[2];
    const float* bk = (const float*)d_in[3];
    const float* Wq = (const float*)d_in[4];
    const float* bq = (const float*)d_in[5];
    const float* Wv = (const float*)d_in[6];
    const float* bv = (const float*)d_in[7];
    const float* Wr = (const float*)d_in[8];
    const float* br = (const float*)d_in[9];
    float* out = (float*)d_out;

    const int SMEM_A = (2 * CH * TS + CH * WST) * (int)sizeof(uint32_t);            // 184,320
    const int SMEM_B = (2 * CH * TS + CH * WST + NHEAD * HK * HK) * (int)sizeof(float); // 217,088
    cudaFuncSetAttribute(fused_kv_ctx_kernel, cudaFuncAttributeMaxDynamicSharedMemorySize, SMEM_A);
    cudaFuncSetAttribute(tail_kernel,         cudaFuncAttributeMaxDynamicSharedMemorySize, SMEM_B);

    zero_acc_kernel<<<(NB * NHEAD * HK * HK + 255) / 256, 256>>>();
    fused_kv_ctx_kernel<<<dim3(NLT, NB), 256, SMEM_A>>>(context_, Wk, bk, Wv, bv);
    tail_kernel<<<dim3(NLT, NB), 256, SMEM_B>>>(input_, Wq, bq, Wr, br, out);
}

// round 6
// speedup vs baseline: 4.1480x; 2.4306x over previous
#include <cuda_runtime.h>
#include <cuda_fp16.h>
#include <cstdint>

// Problem constants (fixed by the dataset)
#define NB    16
#define CH    256
#define LPIX  9216          // 96*96
#define NHEAD 8
#define HK    32            // CH / NHEAD
#define LT    64            // pixel tile per block
#define NLT   144           // LPIX / LT
#define TS    72            // half-stride of [ch][pix] tiles (64 + 8 pad) -> conflict-free
#define WSS   40            // half-stride of W staging rows (32 + 8 pad) -> conflict-free

// Scratch (allocation-free rule: __device__ globals)
__device__ __half g_Wh[4 * CH * CH];            // pre-converted W, tile-major [mat][kt][o][32]
__device__ float  g_num[NB * NHEAD * HK * HK];  // sum_l e^K[k,l] * V[v,l]
__device__ float  g_den[NB * CH];               // sum_l e^K[k,l]

// ---------------------------------------------------------------------------
// Fast exp on the FMA pipe (37.7M exps; avoids the MUFU throughput wall).
// ---------------------------------------------------------------------------
__device__ __forceinline__ float fexp(float x) {
    const float LOG2E = 1.4426950408889634f;
    const float SHIFT = 12582912.0f;             // 1.5 * 2^23
    float y = x * LOG2E;
    float z = __fadd_rn(y, SHIFT);
    int   n = __float_as_int(z) - 0x4B400000;
    float f = y - __fsub_rn(z, SHIFT);           // [-0.5, 0.5]
    float t = f * 0.6931471805599453f;
    float p = 1.0f + t * (1.0f + t * (0.5f + t * (0.16666667f +
              t * (0.041666667f + t * 0.0083333333f))));
    return __int_as_float((n + 127) << 23) * p;
}

__device__ __forceinline__ uint32_t smem_u32(const void* p) {
    return (uint32_t)__cvta_generic_to_shared(p);
}
__device__ __forceinline__ void cpasync16(uint32_t dst, const void* src) {
    asm volatile("cp.async.ca.shared.global [%0], [%1], 16;\n" :: "r"(dst), "l"(src));
}
#define CP_COMMIT() asm volatile("cp.async.commit_group;\n" ::: "memory")
#define CP_WAIT0()  asm volatile("cp.async.wait_group 0;\n"  ::: "memory")

// m16n8k16 f16 HMMA, fp32 accumulate: C += A*B
__device__ __forceinline__ void mma16(float* c, const uint32_t* a, const uint32_t* b) {
    asm volatile(
        "mma.sync.aligned.m16n8k16.row.col.f32.f16.f16.f32 "
        "{%0,%1,%2,%3},{%4,%5,%6,%7},{%8,%9},{%0,%1,%2,%3};\n"
        : "+f"(c[0]), "+f"(c[1]), "+f"(c[2]), "+f"(c[3])
        : "r"(a[0]), "r"(a[1]), "r"(a[2]), "r"(a[3]), "r"(b[0]), "r"(b[1]));
}
// 2x 8x8 b16 matrices, transposed at load: the .col B fragment from [k][n] rows
__device__ __forceinline__ void ldmx2t(uint32_t& d0, uint32_t& d1, uint32_t addr) {
    asm volatile("ldmatrix.sync.aligned.m8n8.x2.trans.shared.b16 {%0,%1}, [%2];\n"
                 : "=r"(d0), "=r"(d1) : "r"(addr));
}

__device__ __forceinline__ void zeroC(float C[4][4][4]) {
    #pragma unroll
    for (int i = 0; i < 4; ++i)
        #pragma unroll
        for (int j = 0; j < 4; ++j)
            #pragma unroll
            for (int k = 0; k < 4; ++k) C[i][j][k] = 0.0f;
}

// ---------------------------------------------------------------------------
// f16 tensor-core GEMM tile: C[256(cout) x 64(pix)] += W @ Bs.
// Wt: tile-major pre-converted half W: [8 ktiles][256 o][32 k].
// Ws: double-buffered staging [2][256][WSS]; filled via cp.async, prefetching
// tile kt+1 behind the compute of tile kt. One barrier per k-tile.
// Bs: half [256 ch][TS] rows, pix contiguous; B frags via ldmatrix.trans.
// 8 warps = 4(m) x 2(n); warp tile 64x32.  NO trailing sync.
// ---------------------------------------------------------------------------
__device__ __forceinline__ void stage_w(const __half* Wt, int kt, int buf,
                                        uint32_t Ws_b, int tid) {
    const __half* src = Wt + kt * 8192 + tid * 32;
    uint32_t dst = Ws_b + buf * 20480 + tid * 80;
    cpasync16(dst,      src);
    cpasync16(dst + 16, src + 8);
    cpasync16(dst + 32, src + 16);
    cpasync16(dst + 48, src + 24);
    CP_COMMIT();
}

__device__ __forceinline__ void gemm_f16(
    const __half* __restrict__ Wt, __half* Ws, uint32_t Ws_b,
    uint32_t Bs_b, int tid, int m_warp, int n_warp, int q, int r, int lane16,
    float C[4][4][4])
{
    stage_w(Wt, 0, 0, Ws_b, tid);
    for (int kt = 0; kt < 8; ++kt) {
        CP_WAIT0();
        __syncthreads();                          // tile kt landed; prev compute done
        if (kt < 7) stage_w(Wt, kt + 1, (kt + 1) & 1, Ws_b, tid);
        const uint32_t* Wb = reinterpret_cast<const uint32_t*>(Ws + (kt & 1) * 10240);
        #pragma unroll
        for (int ks = 0; ks < 2; ++ks) {
            const int kk = ks * 16;
            uint32_t a[4][4], b[4][2];
            #pragma unroll
            for (int mi = 0; mi < 4; ++mi) {
                const uint32_t* ap = Wb + (m_warp + mi * 16 + q) * (WSS / 2) + (kk >> 1) + r;
                a[mi][0] = ap[0];
                a[mi][1] = ap[8 * (WSS / 2)];
                a[mi][2] = ap[4];
                a[mi][3] = ap[8 * (WSS / 2) + 4];
            }
            #pragma unroll
            for (int ni = 0; ni < 4; ++ni) {
                uint32_t p = Bs_b + ((kt * 32 + kk + lane16) * TS + n_warp + ni * 8) * 2;
                ldmx2t(b[ni][0], b[ni][1], p);
            }
            #pragma unroll
            for (int mi = 0; mi < 4; ++mi)
                #pragma unroll
                for (int ni = 0; ni < 4; ++ni)
                    mma16(C[mi][ni], a[mi], b[ni]);
        }
    }
}

// ---------------------------------------------------------------------------
// Prep: convert all four W matrices to half, tile-major. mats: 0=Wk 1=Wv 2=Wq 3=Wr
// ---------------------------------------------------------------------------
__global__ void prep_w_kernel(const float* __restrict__ Wk, const float* __restrict__ Wv,
                              const float* __restrict__ Wq, const float* __restrict__ Wr)
{
    int b = blockIdx.x;                  // 1024 blocks
    int mat = b >> 8, o = b & 255, k = threadIdx.x;
    const float* W = (mat == 0) ? Wk : (mat == 1) ? Wv : (mat == 2) ? Wq : Wr;
    float v = W[o * CH + k];
    int kt = k >> 5, kk = k & 31;
    g_Wh[mat * 65536 + kt * 8192 + o * 32 + kk] = __float2half_rn(v);
}

__global__ void zero_acc_kernel() {
    int i = blockIdx.x * blockDim.x + threadIdx.x;
    if (i < NB * NHEAD * HK * HK) g_num[i] = 0.0f;
    if (i < NB * CH)              g_den[i] = 0.0f;
}

// ---------------------------------------------------------------------------
// Kernel A: per 64-pixel tile:  K = Wk@ctx+bk -> e^K (half);  V = Wv@ctx+bv
// (overwrites the context tile);  per-head partial num = e^K @ V^T via mma;
// partial den = row sums.  atomicAdd into g_num/g_den.  K/V never touch HBM.
// ---------------------------------------------------------------------------
__global__ void __launch_bounds__(256, 2)
kernelA(const float* __restrict__ ctxt,
        const float* __restrict__ bk, const float* __restrict__ bv)
{
    extern __shared__ __align__(16) unsigned char smraw[];
    __half* Xs = reinterpret_cast<__half*>(smraw);           // [256][TS] ctx, then V
    __half* Es = Xs + CH * TS;                               // [256][TS] e^K
    __half* Ws = Es + CH * TS;                               // [2][256][WSS]
    const uint32_t Xs_b = smem_u32(Xs), Ws_b = smem_u32(Ws);

    const int tid = threadIdx.x;
    const int lane = tid & 31, wid = tid >> 5;
    const int q = lane >> 2, r = lane & 3, lane16 = lane & 15;
    const int m_warp = (wid >> 1) * 64, n_warp = (wid & 1) * 32;
    const int lt = blockIdx.x, n = blockIdx.y, l0 = lt * LT;

    // load context tile as half [ch][pix]
    const float* src = ctxt + (size_t)n * CH * LPIX + l0;
    #pragma unroll 4
    for (int idx = tid; idx < CH * LT / 4; idx += 256) {
        int c = idx >> 4, p4 = (idx & 15) << 2;
        float4 v = *reinterpret_cast<const float4*>(src + (size_t)c * LPIX + p4);
        __half2* d = reinterpret_cast<__half2*>(Xs + c * TS + p4);
        d[0] = __floats2half2_rn(v.x, v.y);
        d[1] = __floats2half2_rn(v.z, v.w);
    }
    __syncthreads();

    float C[4][4][4];

    // ---- K projection -> e^K (half) + den partials
    zeroC(C);
    gemm_f16(g_Wh + 0 * 65536, Ws, Ws_b, Xs_b, tid, m_warp, n_warp, q, r, lane16, C);
    #pragma unroll
    for (int mi = 0; mi < 4; ++mi) {
        int row = m_warp + mi * 16 + q;
        float b0v = __ldg(&bk[row]), b8v = __ldg(&bk[row + 8]);
        float s0 = 0.f, s8 = 0.f;
        #pragma unroll
        for (int ni = 0; ni < 4; ++ni) {
            int col = n_warp + ni * 8 + 2 * r;
            __half2 h01 = __floats2half2_rn(fexp(C[mi][ni][0] + b0v), fexp(C[mi][ni][1] + b0v));
            __half2 h23 = __floats2half2_rn(fexp(C[mi][ni][2] + b8v), fexp(C[mi][ni][3] + b8v));
            *reinterpret_cast<__half2*>(Es + row * TS + col)       = h01;
            *reinterpret_cast<__half2*>(Es + (row + 8) * TS + col) = h23;
            float2 f01 = __half22float2(h01), f23 = __half22float2(h23);
            s0 += f01.x + f01.y;                 // den from the SAME half-rounded values
            s8 += f23.x + f23.y;
        }
        s0 += __shfl_xor_sync(0xffffffffu, s0, 1); s0 += __shfl_xor_sync(0xffffffffu, s0, 2);
        s8 += __shfl_xor_sync(0xffffffffu, s8, 1); s8 += __shfl_xor_sync(0xffffffffu, s8, 2);
        if (r == 0) {
            atomicAdd(&g_den[n * CH + row],     s0);
            atomicAdd(&g_den[n * CH + row + 8], s8);
        }
    }

    // ---- V projection (reads Xs) ...
    zeroC(C);
    gemm_f16(g_Wh + 1 * 65536, Ws, Ws_b, Xs_b, tid, m_warp, n_warp, q, r, lane16, C);
    __syncthreads();                              // all warps done reading Xs
    #pragma unroll
    for (int mi = 0; mi < 4; ++mi) {              // ... then overwrite Xs with V (half)
        int row = m_warp + mi * 16 + q;
        float b0v = __ldg(&bv[row]), b8v = __ldg(&bv[row + 8]);
        #pragma unroll
        for (int ni = 0; ni < 4; ++ni) {
            int col = n_warp + ni * 8 + 2 * r;
            *reinterpret_cast<__half2*>(Xs + row * TS + col) =
                __floats2half2_rn(C[mi][ni][0] + b0v, C[mi][ni][1] + b0v);
            *reinterpret_cast<__half2*>(Xs + (row + 8) * TS + col) =
                __floats2half2_rn(C[mi][ni][2] + b8v, C[mi][ni][3] + b8v);
        }
    }
    __syncthreads();                              // Es + V visible everywhere

    // ---- partial numerator: warp h:  num_h[32][32] += Es_h @ V_h^T  (k = 64 pixels)
    {
        const int h = wid;
        #pragma unroll
        for (int i = 0; i < 2; ++i)
            #pragma unroll
            for (int j = 0; j < 4; ++j)
                #pragma unroll
                for (int k = 0; k < 4; ++k) C[i][j][k] = 0.0f;

        const uint32_t* Eh = reinterpret_cast<const uint32_t*>(Es + h * HK * TS);
        const uint32_t* Vh = reinterpret_cast<const uint32_t*>(Xs + h * HK * TS);
        #pragma unroll
        for (int ks = 0; ks < 4; ++ks) {
            const int kw = ks * 8;                // k offset in 32-bit words (16 pixels)
            uint32_t a[2][4], b[4][2];
            #pragma unroll
            for (int mi = 0; mi < 2; ++mi) {
                const uint32_t* ap = Eh + (mi * 16 + q) * (TS / 2) + kw + r;
                a[mi][0] = ap[0];            a[mi][1] = ap[8 * (TS / 2)];
                a[mi][2] = ap[4];            a[mi][3] = ap[8 * (TS / 2) + 4];
            }
            #pragma unroll
            for (int ni = 0; ni < 4; ++ni) {
                const uint32_t* bp = Vh + (ni * 8 + q) * (TS / 2) + kw + r;
                b[ni][0] = bp[0];            b[ni][1] = bp[4];
            }
            #pragma unroll
            for (int mi = 0; mi < 2; ++mi)
                #pragma unroll
                for (int ni = 0; ni < 4; ++ni)
                    mma16(C[mi][ni], a[mi], b[ni]);
        }

        float* base = g_num + ((size_t)(n * NHEAD + h) << 10);
        #pragma unroll
        for (int mi = 0; mi < 2; ++mi) {
            int k0 = mi * 16 + q;
            #pragma unroll
            for (int ni = 0; ni < 4; ++ni) {
                int v0 = ni * 8 + 2 * r;
                atomicAdd(base +  k0      * HK + v0,     C[mi][ni][0]);
                atomicAdd(base +  k0      * HK + v0 + 1, C[mi][ni][1]);
                atomicAdd(base + (k0 + 8) * HK + v0,     C[mi][ni][2]);
                atomicAdd(base + (k0 + 8) * HK + v0 + 1, C[mi][ni][3]);
            }
        }
    }
}

// ---------------------------------------------------------------------------
// Kernel B: per 64-pixel tile:
//   Cst[h][v][k] = (g_num/g_den)^T (half);  Q = Wq@x+bq -> e^Q (half, in place)
//   + per-(head,pixel) sums via smem atomics;  agg = Cst @ e^Q via mma, scaled
//   by 1/sum (in place);  out = Wr@agg + br + x (residual re-read from HBM).
// ---------------------------------------------------------------------------
__global__ void __launch_bounds__(256, 2)
kernelB(const float* __restrict__ input,
        const float* __restrict__ bq, const float* __restrict__ br,
        float* __restrict__ out)
{
    extern __shared__ __align__(16) unsigned char smraw[];
    __half* Xs  = reinterpret_cast<__half*>(smraw);          // [256][TS] x -> e^Q -> agg
    __half* Ws  = Xs + CH * TS;                              // [2][256][WSS]
    __half* Cst = Ws + 2 * CH * WSS;                         // [8][32 v][WSS] ctx^T
    float*  ssum = reinterpret_cast<float*>(Cst + NHEAD * HK * WSS);  // [8][64]
    const uint32_t Xs_b = smem_u32(Xs), Ws_b = smem_u32(Ws);

    const int tid = threadIdx.x;
    const int lane = tid & 31, wid = tid >> 5;
    const int q = lane >> 2, r = lane & 3, lane16 = lane & 15;
    const int m_warp = (wid >> 1) * 64, n_warp = (wid & 1) * 32;
    const int lt = blockIdx.x, n = blockIdx.y, l0 = lt * LT;

    // normalized, transposed context -> half
    {
        const float* numb = g_num + ((size_t)(n * NHEAD) << 10);
        const float* denb = g_den + n * CH;
        #pragma unroll 4
        for (int i = tid; i < NHEAD * HK * HK; i += 256) {
            int h = i >> 10, k = (i >> 5) & 31, v = i & 31;
            float val = __fdividef(numb[i], denb[h * HK + k]);
            Cst[(h * HK + v) * WSS + k] = __float2half_rn(val);
        }
    }
    // input tile as half [ch][pix]
    const float* xin = input + (size_t)n * CH * LPIX + l0;
    #pragma unroll 4
    for (int idx = tid; idx < CH * LT / 4; idx += 256) {
        int c = idx >> 4, p4 = (idx & 15) << 2;
        float4 v = *reinterpret_cast<const float4*>(xin + (size_t)c * LPIX + p4);
        __half2* d = reinterpret_cast<__half2*>(Xs + c * TS + p4);
        d[0] = __floats2half2_rn(v.x, v.y);
        d[1] = __floats2half2_rn(v.z, v.w);
    }
    ssum[tid] = 0.0f; ssum[tid + 256] = 0.0f;
    __syncthreads();

    float C[4][4][4];

    // ---- GEMM 1: Q = Wq @ x + bq
    zeroC(C);
    gemm_f16(g_Wh + 2 * 65536, Ws, Ws_b, Xs_b, tid, m_warp, n_warp, q, r, lane16, C);
    __syncthreads();                              // all warps done reading Xs
    #pragma unroll
    for (int mi = 0; mi < 4; ++mi) {              // e^Q -> Xs + per-(h,pix) sums
        int row = m_warp + mi * 16 + q;
        int h0 = row >> 5, h8 = (row + 8) >> 5;
        float b0v = __ldg(&bq[row]), b8v = __ldg(&bq[row + 8]);
        #pragma unroll
        for (int ni = 0; ni < 4; ++ni) {
            int col = n_warp + ni * 8 + 2 * r;
            __half2 h01 = __floats2half2_rn(fexp(C[mi][ni][0] + b0v), fexp(C[mi][ni][1] + b0v));
            __half2 h23 = __floats2half2_rn(fexp(C[mi][ni][2] + b8v), fexp(C[mi][ni][3] + b8v));
            *reinterpret_cast<__half2*>(Xs + row * TS + col)       = h01;
            *reinterpret_cast<__half2*>(Xs + (row + 8) * TS + col) = h23;
            float2 f01 = __half22float2(h01), f23 = __half22float2(h23);
            atomicAdd(&ssum[h0 * LT + col],     f01.x);
            atomicAdd(&ssum[h0 * LT + col + 1], f01.y);
            atomicAdd(&ssum[h8 * LT + col],     f23.x);
            atomicAdd(&ssum[h8 * LT + col + 1], f23.y);
        }
    }
    __syncthreads();                              // e^Q + sums complete

    // ---- agg mma: warp h:  agg[32 v][64 pix] = Cst_h @ e^Q_h, scaled by 1/sum.
    // Warp h touches ONLY rows h*32..h*32+31 of Xs (reads then writes): no sync.
    {
        const int h = wid;
        zeroC(C);                                 // reused as cc[mi][ni] = C[mi*2+(ni>>2)][ni&3]
        const uint32_t* Ch = reinterpret_cast<const uint32_t*>(Cst + h * HK * WSS);
        #pragma unroll
        for (int ks = 0; ks < 2; ++ks) {
            const int kk = ks * 16;
            uint32_t a[2][4], b0, b1;
            #pragma unroll
            for (int mi = 0; mi < 2; ++mi) {
                const uint32_t* ap = Ch + (mi * 16 + q) * (WSS / 2) + (kk >> 1) + r;
                a[mi][0] = ap[0];            a[mi][1] = ap[8 * (WSS / 2)];
                a[mi][2] = ap[4];            a[mi][3] = ap[8 * (WSS / 2) + 4];
            }
            #pragma unroll
            for (int ni = 0; ni < 8; ++ni) {
                uint32_t p = Xs_b + ((h * HK + kk + lane16) * TS + ni * 8) * 2;
                ldmx2t(b0, b1, p);
                uint32_t bb[2] = {b0, b1};
                mma16(C[0 * 2 + (ni >> 2)][ni & 3], a[0], bb);
                mma16(C[1 * 2 + (ni >> 2)][ni & 3], a[1], bb);
            }
        }
        #pragma unroll
        for (int mi = 0; mi < 2; ++mi) {
            int vrow = h * HK + mi * 16 + q;
            #pragma unroll
            for (int ni = 0; ni < 8; ++ni) {
                int col = ni * 8 + 2 * r;
                float is0 = __fdividef(1.0f, ssum[h * LT + col]);
                float is1 = __fdividef(1.0f, ssum[h * LT + col + 1]);
                const float* cc = C[mi * 2 + (ni >> 2)][ni & 3];
                *reinterpret_cast<__half2*>(Xs + vrow * TS + col) =
                    __floats2half2_rn(cc[0] * is0, cc[1] * is1);
                *reinterpret_cast<__half2*>(Xs + (vrow + 8) * TS + col) =
                    __floats2half2_rn(cc[2] * is0, cc[3] * is1);
            }
        }
    }
    // gemm's first internal barrier orders agg writes before B reads

    // ---- GEMM 2: out = Wr @ agg + br + x (residual reloaded from HBM)
    zeroC(C);
    gemm_f16(g_Wh + 3 * 65536, Ws, Ws_b, Xs_b, tid, m_warp, n_warp, q, r, lane16, C);
    #pragma unroll
    for (int mi = 0; mi < 4; ++mi) {
        int row = m_warp + mi * 16 + q;
        float b0v = __ldg(&br[row]), b8v = __ldg(&br[row + 8]);
        #pragma unroll
        for (int ni = 0; ni < 4; ++ni) {
            int col = n_warp + ni * 8 + 2 * r;
            float2 x0 = *reinterpret_cast<const float2*>(xin + (size_t)row * LPIX + col);
            float2 x8 = *reinterpret_cast<const float2*>(xin + (size_t)(row + 8) * LPIX + col);
            float2 o0 = make_float2(C[mi][ni][0] + b0v + x0.x, C[mi][ni][1] + b0v + x0.y);
            float2 o8 = make_float2(C[mi][ni][2] + b8v + x8.x, C[mi][ni][3] + b8v + x8.y);
            *reinterpret_cast<float2*>(out + (size_t)(n * CH + row) * LPIX + l0 + col) = o0;
            *reinterpret_cast<float2*>(out + (size_t)(n * CH + row + 8) * LPIX + l0 + col) = o8;
        }
    }
}

// ---------------------------------------------------------------------------
extern "C" void kernel_launch(void* const* d_in, const int* in_sizes, int n_in,
                              void* d_out, int out_size)
{
    (void)in_sizes; (void)n_in; (void)out_size;
    const float* input_   = (const float*)d_in[0];
    const float* context_ = (const float*)d_in[1];
    const float* Wk = (const float*)d_in[2];
    const float* bk = (const float*)d_in[3];
    const float* Wq = (const float*)d_in[4];
    const float* bq = (const float*)d_in[5];
    const float* Wv = (const float*)d_in[6];
    const float* bv = (const float*)d_in[7];
    const float* Wr = (const float*)d_in[8];
    const float* br = (const float*)d_in[9];
    float* out = (float*)d_out;

    const int SMEM_A = (2 * CH * TS + 2 * CH * WSS) * 2;                       // 114,688
    const int SMEM_B = (CH * TS + 2 * CH * WSS + NHEAD * HK * WSS) * 2
                       + NHEAD * LT * (int)sizeof(float);                      // 100,352
    cudaFuncSetAttribute(kernelA, cudaFuncAttributeMaxDynamicSharedMemorySize, SMEM_A);
    cudaFuncSetAttribute(kernelB, cudaFuncAttributeMaxDynamicSharedMemorySize, SMEM_B);

    prep_w_kernel<<<1024, 256>>>(Wk, Wv, Wq, Wr);
    zero_acc_kernel<<<(NB * NHEAD * HK * HK + 255) / 256, 256>>>();
    kernelA<<<dim3(NLT, NB), 256, SMEM_A>>>(context_, bk, bv);
    kernelB<<<dim3(NLT, NB), 256, SMEM_B>>>(input_, bq, br, out);
}